// round 16
// baseline (speedup 1.0000x reference)
#include <cuda_runtime.h>

// CRF forward (log-partition) minus gold-path score — IMMA edition, v8.
//
// Exp-domain chunked chains: u_t = diag(exp(feat_t)) * E * u_{t-1}.
// E = exp(T) quantized per-row to s8 (0..127); state requantized to s8 each
// step; per-step log-growth telescoped exactly for the quantized shadow chain.
//
// v8 vs v7: software-pipelined dual chain-groups in one 512-thread CTA
// (1 CTA/SM, NCH=16 = groups A+B). Per step: GEMM_A issues, reduceB(s-1)
// runs under it; GEMM_B issues, epilogue_A runs under it; only epilogue_B +
// reduceA are exposed -> tensor util 80% -> ~87%. gold_kernel folded into
// the chunk prologue (one fewer launch). Same chain-steps (35520), BURN=1.

#define LNUM  512
#define NCTA  148                 // 1 per SM
#define NCH   16                  // chains per CTA: group A = 0..7, B = 8..15
#define NCHUNK (NCTA * NCH)       // 2368
#define BURN  1
#define VPITCH 528                // vq row pitch (B-fragment reads conflict-free)
#define ZP     516                // zbuf row pitch (epilogue scatter conflict-free)

// Device scratch (static; no allocation allowed).
__device__ __align__(16) unsigned char g_A[LNUM * LNUM];  // E s8, A-fragment order
__device__ float g_rs[LNUM];
__device__ float g_acc[NCHUNK];
__device__ float g_gold_part[NCTA];
__device__ unsigned g_ctr = 0;    // last-CTA election; self-resets each run

// ---------------------------------------------------------------------------
__device__ __forceinline__ float warpSum(float x) {
#pragma unroll
    for (int o = 16; o; o >>= 1) x += __shfl_xor_sync(0xffffffffu, x, o);
    return x;
}
__device__ __forceinline__ float warpMax(float x) {
#pragma unroll
    for (int o = 16; o; o >>= 1) x = fmaxf(x, __shfl_xor_sync(0xffffffffu, x, o));
    return x;
}

__device__ __forceinline__ void imma(int& d0, int& d1, int& d2, int& d3,
                                     unsigned a0, unsigned a1, unsigned a2, unsigned a3,
                                     unsigned b0, unsigned b1) {
    asm volatile(
        "mma.sync.aligned.m16n8k32.row.col.s32.s8.s8.s32 "
        "{%0,%1,%2,%3},{%4,%5,%6,%7},{%8,%9},{%0,%1,%2,%3};"
        : "+r"(d0), "+r"(d1), "+r"(d2), "+r"(d3)
        : "r"(a0), "r"(a1), "r"(a2), "r"(a3), "r"(b0), "r"(b1));
}

// ---------------------------------------------------------------------------
// Prep: block = row j. 128 threads: row max, rs_j, quantize row into the
// mma.m16n8k32 A-fragment layout (verified R6-R14). Thread k4 emits one u32.
// ---------------------------------------------------------------------------
__global__ void prep_kernel(const float* __restrict__ T) {
    __shared__ float red[4];
    __shared__ float s_mx;
    const int j   = blockIdx.x;
    const int tid = threadIdx.x;           // 0..127 == k4
    const float4 tv = reinterpret_cast<const float4*>(T + j * LNUM)[tid];

    float m = fmaxf(fmaxf(tv.x, tv.y), fmaxf(tv.z, tv.w));
    m = warpMax(m);
    if ((tid & 31) == 0) red[tid >> 5] = m;
    __syncthreads();
    if (tid == 0) {
        float mm = fmaxf(fmaxf(red[0], red[1]), fmaxf(red[2], red[3]));
        s_mx = mm;
        g_rs[j] = expf(mm) / 127.f;
    }
    __syncthreads();
    const float mx = s_mx;

    unsigned w = 0;
    w |= (unsigned)min(__float2int_rn(expf(tv.x - mx) * 127.f), 127);
    w |= (unsigned)min(__float2int_rn(expf(tv.y - mx) * 127.f), 127) << 8;
    w |= (unsigned)min(__float2int_rn(expf(tv.z - mx) * 127.f), 127) << 16;
    w |= (unsigned)min(__float2int_rn(expf(tv.w - mx) * 127.f), 127) << 24;

    int m16 = j >> 4, r = j & 15, gid = r & 7, rh = r >> 3;
    int kc  = tid >> 3;
    int tig = (tid & 7) & 3;
    int kh  = (tid & 7) >> 2;
    reinterpret_cast<unsigned*>(g_A)[((m16 * 16 + kc) * 32 + gid * 4 + tig) * 4 +
                                     (rh + 2 * kh)] = w;
}

// ---------------------------------------------------------------------------
// Main: one CTA = 16 chains (A: 0-7, B: 8-15), 512 threads = 16 warps,
// 1 CTA/SM. GEMM: warp w owns mtiles {2w, 2w+1}. Reduce: warp w owns chain w.
// Pipelined: reduceB(s-1) under GEMM_A(s); epilogueA(s) under GEMM_B(s).
// ---------------------------------------------------------------------------
__global__ void __launch_bounds__(512, 1)
chunk_kernel(const float* __restrict__ logit, const int* __restrict__ labels,
             const float* __restrict__ T, float* __restrict__ out,
             int S, int K) {
    __shared__ __align__(16) unsigned char vq[NCH * VPITCH];  // 8448 B
    __shared__ __align__(16) float zbuf[NCH * ZP];            // 33024 B
    __shared__ float s_rs[LNUM];
    __shared__ float s_red[16];
    __shared__ float s_m, s_s0;
    __shared__ int   s_last;
    __shared__ double sd[256];

    const int tid  = threadIdx.x;
    const int wid  = tid >> 5;          // 0..15
    const int lane = tid & 31;
    const int gid  = lane >> 2;
    const int tig  = lane & 3;

    s_rs[tid] = g_rs[tid];

    // --- gold-path partial for this CTA (folded-in; deterministic) ---
    {
        float p = 0.f;
        for (int t = blockIdx.x * 512 + tid; t < S; t += NCTA * 512) {
            int lt = labels[t];
            p += logit[(t << 9) + lt];
            if (t >= 1) p += T[(lt << 9) + labels[t - 1]];
        }
        p = warpSum(p);
        if (lane == 0) s_red[wid] = p;
        __syncthreads();
        if (wid == 0) {
            float s2 = (lane < 16) ? s_red[lane] : 0.f;
            s2 = warpSum(s2);
            if (lane == 0) g_gold_part[blockIdx.x] = s2;
        }
        __syncthreads();
    }

    // --- warp-as-chain schedule (chain wid, 0..15) ---
    const int cg_w   = blockIdx.x * NCH + wid;
    const int own_w  = 1 + cg_w * K;
    const int tend_w = min(own_w + K, S);
    const int t0_w   = (cg_w == 0) ? 1 : own_w - BURN;

    // --- epilogue chains for this thread: A: 2tig+q ; B: 8+2tig+q ---
    int t0A[2], teA[2], t0B[2], teB[2];
#pragma unroll
    for (int q = 0; q < 2; ++q) {
        int ca = blockIdx.x * NCH + 2 * tig + q;
        int oa = 1 + ca * K;
        teA[q] = min(oa + K, S);
        t0A[q] = (ca == 0) ? 1 : oa - BURN;
        int cb = blockIdx.x * NCH + 8 + 2 * tig + q;
        int ob = 1 + cb * K;
        teB[q] = min(ob + K, S);
        t0B[q] = ob - BURN;                // chain>=8 is never chain 0
    }

    // --- init: uniform state everywhere ---
#pragma unroll
    for (int c = 0; c < NCH; ++c) vq[c * VPITCH + tid] = 127;
    __syncthreads();

    float sw_reg = 127.f * (float)LNUM;
    float accr   = 0.f;                    // lane 0 of warp wid

    // --- chain 0 exact start from exp(feat_0) (block 0 only) ---
    if (blockIdx.x == 0) {
        float f = logit[tid];
        float m = warpMax(f);
        if (lane == 0) s_red[wid] = m;
        __syncthreads();
        if (wid == 0) {
            float mm = (lane < 16) ? s_red[lane] : -1e30f;
            mm = warpMax(mm);
            if (lane == 0) s_m = mm;
        }
        __syncthreads();
        int wi = min(__float2int_rn(expf(f - s_m) * 127.f), 127);
        vq[tid] = (unsigned char)wi;
        float sw = warpSum((float)wi);
        if (lane == 0) s_red[wid] = sw;
        __syncthreads();
        if (wid == 0) {
            float s2 = (lane < 16) ? s_red[lane] : 0.f;
            s2 = warpSum(s2);
            if (lane == 0) s_s0 = s2;
        }
        __syncthreads();
        if (wid == 0) {
            sw_reg = s_s0;
            if (lane == 0) accr = s_m - logf(127.f) + logf(s_s0);
        }
        __syncthreads();
    }

    const uint4* __restrict__ A4 = reinterpret_cast<const uint4*>(g_A);
    const int m0 = wid * 2, m1 = wid * 2 + 1;
    const int jl0 = m0 * 16 + gid, jl1 = jl0 + 8;
    const int jl2 = m1 * 16 + gid, jl3 = jl2 + 8;
    const float rl0 = s_rs[jl0], rh0 = s_rs[jl1];
    const float rl1 = s_rs[jl2], rh1 = s_rs[jl3];
    const int steps = BURN + K;            // 15

    for (int s = 0; s <= steps; ++s) {
        const bool run = (s < steps);
        int dA[2][4], dB[2][4];
        float fvA[2][4], fvB[2][4];
        bool  actA[2], actB[2];

        // ---- phase 1: issue GEMM_A; reduceB(s-1) overlaps its execution ----
        if (run) {
#pragma unroll
            for (int mi = 0; mi < 2; ++mi)
#pragma unroll
                for (int r = 0; r < 4; ++r) dA[mi][r] = 0;
#pragma unroll
            for (int kc = 0; kc < 16; ++kc) {
                const int kb = kc * 32 + tig * 4;
                unsigned b0 = *reinterpret_cast<const unsigned*>(&vq[gid * VPITCH + kb]);
                unsigned b1 = *reinterpret_cast<const unsigned*>(&vq[gid * VPITCH + kb + 16]);
                uint4 A0 = A4[(m0 * 16 + kc) * 32 + lane];
                uint4 A1 = A4[(m1 * 16 + kc) * 32 + lane];
                imma(dA[0][0], dA[0][1], dA[0][2], dA[0][3], A0.x, A0.y, A0.z, A0.w, b0, b1);
                imma(dA[1][0], dA[1][1], dA[1][2], dA[1][3], A1.x, A1.y, A1.z, A1.w, b0, b1);
            }
#pragma unroll
            for (int q = 0; q < 2; ++q) {
                int t = t0A[q] + s;
                actA[q] = (t < teA[q]);
                if (actA[q]) {
                    const float* lt = logit + ((long)t << 9);
                    fvA[q][0] = lt[jl0]; fvA[q][1] = lt[jl1];
                    fvA[q][2] = lt[jl2]; fvA[q][3] = lt[jl3];
                }
            }
        }
        if (s > 0 && wid >= 8) {           // reduce+requant chain wid (group B), step s-1
            int t = t0_w + (s - 1);
            if (t < tend_w) {
                const float* zr = zbuf + wid * ZP;
                const float4* zb = reinterpret_cast<const float4*>(zr + lane * 16);
                float4 z0 = zb[0], z1 = zb[1], z2 = zb[2], z3 = zb[3];
                float mx = fmaxf(fmaxf(fmaxf(z0.x, z0.y), fmaxf(z0.z, z0.w)),
                                 fmaxf(fmaxf(z1.x, z1.y), fmaxf(z1.z, z1.w)));
                mx = fmaxf(mx, fmaxf(fmaxf(fmaxf(z2.x, z2.y), fmaxf(z2.z, z2.w)),
                                     fmaxf(fmaxf(z3.x, z3.y), fmaxf(z3.z, z3.w))));
                float sm = ((z0.x + z0.y) + (z0.z + z0.w)) +
                           ((z1.x + z1.y) + (z1.z + z1.w)) +
                           ((z2.x + z2.y) + (z2.z + z2.w)) +
                           ((z3.x + z3.y) + (z3.z + z3.w));
                mx = warpMax(mx);
                sm = warpSum(sm);
                float bcv = 127.f / mx;
                unsigned pk[4];
                int lsum = 0;
#pragma unroll
                for (int p = 0; p < 4; ++p) {
                    float4 z = (p == 0) ? z0 : (p == 1) ? z1 : (p == 2) ? z2 : z3;
                    int w0 = min(__float2int_rn(z.x * bcv), 127);
                    int w1 = min(__float2int_rn(z.y * bcv), 127);
                    int w2 = min(__float2int_rn(z.z * bcv), 127);
                    int w3 = min(__float2int_rn(z.w * bcv), 127);
                    lsum += w0 + w1 + w2 + w3;
                    pk[p] = (unsigned)w0 | ((unsigned)w1 << 8) |
                            ((unsigned)w2 << 16) | ((unsigned)w3 << 24);
                }
                *reinterpret_cast<uint4*>(&vq[wid * VPITCH + lane * 16]) =
                    make_uint4(pk[0], pk[1], pk[2], pk[3]);
                unsigned tot = __reduce_add_sync(0xffffffffu, (unsigned)lsum);
                if (lane == 0 && t >= own_w) accr += logf(sm) - logf(sw_reg);
                sw_reg = (float)tot;
            }
        }
        __syncthreads();                    // vqB ready; zbufB reusable

        // ---- phase 2: issue GEMM_B; epilogue_A overlaps its execution ----
        if (run) {
#pragma unroll
            for (int mi = 0; mi < 2; ++mi)
#pragma unroll
                for (int r = 0; r < 4; ++r) dB[mi][r] = 0;
#pragma unroll
            for (int kc = 0; kc < 16; ++kc) {
                const int kb = kc * 32 + tig * 4;
                unsigned b0 = *reinterpret_cast<const unsigned*>(&vq[(8 + gid) * VPITCH + kb]);
                unsigned b1 = *reinterpret_cast<const unsigned*>(&vq[(8 + gid) * VPITCH + kb + 16]);
                uint4 A0 = A4[(m0 * 16 + kc) * 32 + lane];
                uint4 A1 = A4[(m1 * 16 + kc) * 32 + lane];
                imma(dB[0][0], dB[0][1], dB[0][2], dB[0][3], A0.x, A0.y, A0.z, A0.w, b0, b1);
                imma(dB[1][0], dB[1][1], dB[1][2], dB[1][3], A1.x, A1.y, A1.z, A1.w, b0, b1);
            }
#pragma unroll
            for (int q = 0; q < 2; ++q) {
                int t = t0B[q] + s;
                actB[q] = (t < teB[q]);
                if (actB[q]) {
                    const float* lt = logit + ((long)t << 9);
                    fvB[q][0] = lt[jl0]; fvB[q][1] = lt[jl1];
                    fvB[q][2] = lt[jl2]; fvB[q][3] = lt[jl3];
                }
            }
            // epilogue A (depends on dA only; tensor pipe busy with GEMM_B)
#pragma unroll
            for (int q = 0; q < 2; ++q) {
                if (actA[q]) {
                    float* zr = zbuf + (2 * tig + q) * ZP;
                    zr[jl0] = __expf(fvA[q][0]) * rl0 * (float)dA[0][q];
                    zr[jl1] = __expf(fvA[q][1]) * rh0 * (float)dA[0][q + 2];
                    zr[jl2] = __expf(fvA[q][2]) * rl1 * (float)dA[1][q];
                    zr[jl3] = __expf(fvA[q][3]) * rh1 * (float)dA[1][q + 2];
                }
            }
        }
        __syncthreads();                    // zbufA ready

        // ---- phase 3: epilogue_B; reduceA (warps 0-7) ----
        if (run) {
#pragma unroll
            for (int q = 0; q < 2; ++q) {
                if (actB[q]) {
                    float* zr = zbuf + (8 + 2 * tig + q) * ZP;
                    zr[jl0] = __expf(fvB[q][0]) * rl0 * (float)dB[0][q];
                    zr[jl1] = __expf(fvB[q][1]) * rh0 * (float)dB[0][q + 2];
                    zr[jl2] = __expf(fvB[q][2]) * rl1 * (float)dB[1][q];
                    zr[jl3] = __expf(fvB[q][3]) * rh1 * (float)dB[1][q + 2];
                }
            }
            if (wid < 8) {                  // reduce+requant chain wid (group A), step s
                int t = t0_w + s;
                if (t < tend_w) {
                    const float* zr = zbuf + wid * ZP;
                    const float4* zb = reinterpret_cast<const float4*>(zr + lane * 16);
                    float4 z0 = zb[0], z1 = zb[1], z2 = zb[2], z3 = zb[3];
                    float mx = fmaxf(fmaxf(fmaxf(z0.x, z0.y), fmaxf(z0.z, z0.w)),
                                     fmaxf(fmaxf(z1.x, z1.y), fmaxf(z1.z, z1.w)));
                    mx = fmaxf(mx, fmaxf(fmaxf(fmaxf(z2.x, z2.y), fmaxf(z2.z, z2.w)),
                                         fmaxf(fmaxf(z3.x, z3.y), fmaxf(z3.z, z3.w))));
                    float sm = ((z0.x + z0.y) + (z0.z + z0.w)) +
                               ((z1.x + z1.y) + (z1.z + z1.w)) +
                               ((z2.x + z2.y) + (z2.z + z2.w)) +
                               ((z3.x + z3.y) + (z3.z + z3.w));
                    mx = warpMax(mx);
                    sm = warpSum(sm);
                    float bcv = 127.f / mx;
                    unsigned pk[4];
                    int lsum = 0;
#pragma unroll
                    for (int p = 0; p < 4; ++p) {
                        float4 z = (p == 0) ? z0 : (p == 1) ? z1 : (p == 2) ? z2 : z3;
                        int w0 = min(__float2int_rn(z.x * bcv), 127);
                        int w1 = min(__float2int_rn(z.y * bcv), 127);
                        int w2 = min(__float2int_rn(z.z * bcv), 127);
                        int w3 = min(__float2int_rn(z.w * bcv), 127);
                        lsum += w0 + w1 + w2 + w3;
                        pk[p] = (unsigned)w0 | ((unsigned)w1 << 8) |
                                ((unsigned)w2 << 16) | ((unsigned)w3 << 24);
                    }
                    *reinterpret_cast<uint4*>(&vq[wid * VPITCH + lane * 16]) =
                        make_uint4(pk[0], pk[1], pk[2], pk[3]);
                    unsigned tot = __reduce_add_sync(0xffffffffu, (unsigned)lsum);
                    if (lane == 0 && t >= own_w) accr += logf(sm) - logf(sw_reg);
                    sw_reg = (float)tot;
                }
            }
        }
        __syncthreads();                    // vqA + zbufB ready for next step
    }

    if (lane == 0) g_acc[cg_w] = accr;

    // ---- last-arriving CTA: deterministic final reduction ----
    __syncthreads();
    if (tid == 0) {
        __threadfence();
        unsigned old = atomicAdd(&g_ctr, 1u);
        s_last = (old == NCTA - 1) ? 1 : 0;
    }
    __syncthreads();
    if (s_last) {
        if (tid < 256) {
            double v = 0.0;
            for (int c = tid; c < NCHUNK; c += 256) v += (double)g_acc[c];
            for (int b = tid; b < NCTA; b += 256) v -= (double)g_gold_part[b];
            sd[tid] = v;
        }
        __syncthreads();
        for (int o = 128; o; o >>= 1) {
            if (tid < o) sd[tid] += sd[tid + o];
            __syncthreads();
        }
        if (tid == 0) {
            out[0] = (float)sd[0];
            g_ctr = 0;                      // reset for next graph replay
        }
    }
}

// ---------------------------------------------------------------------------
extern "C" void kernel_launch(void* const* d_in, const int* in_sizes, int n_in,
                              void* d_out, int out_size) {
    const float* logit  = (const float*)d_in[0];
    const int*   labels = (const int*)d_in[1];
    const float* T      = (const float*)d_in[2];
    const int S = in_sizes[1];                        // 32768
    const int K = (S - 1 + NCHUNK - 1) / NCHUNK;      // 14

    prep_kernel<<<LNUM, 128>>>(T);
    chunk_kernel<<<NCTA, 512>>>(logit, labels, T, (float*)d_out, S, K);
}

// round 17
// speedup vs baseline: 1.0447x; 1.0447x over previous
#include <cuda_runtime.h>

// CRF forward (log-partition) minus gold-path score — IMMA edition, v9.
//
// Exp-domain chunked chains: u_t = diag(exp(feat_t)) * E * u_{t-1}.
// E = exp(T) quantized per-row to s8 (0..127); state requantized to s8 each
// step; per-step log-growth telescoped exactly for the quantized shadow chain.
//
// v9 = v7 (the 159.8us champion: 2 CTAs/SM, NCH=8, BURN=1, fused register
// reduce+requant, last-CTA final reduction) with gold_kernel folded into
// prep_kernel (block j also reduces gold timesteps [64j,64j+64)) — one fewer
// launch. v8's intra-CTA pipelining REGRESSED (util 80->72%): barrier-
// separated phases are only hidden by an independent co-resident CTA.

#define LNUM  512
#define NCTA  296                 // 2 per SM
#define NCH   8                   // chains per CTA (one n8 MMA group)
#define NCHUNK (NCTA * NCH)       // 2368
#define BURN  1
#define GOLD_PARTS 512            // one per prep block
#define VPITCH 528                // vq row pitch (B-fragment reads conflict-free)
#define ZP     516                // zbuf row pitch (epilogue scatter conflict-free)

// Device scratch (static; no allocation allowed).
__device__ __align__(16) unsigned char g_A[LNUM * LNUM];  // E s8, A-fragment order
__device__ float g_rs[LNUM];
__device__ float g_acc[NCHUNK];
__device__ float g_gold_part[GOLD_PARTS];
__device__ unsigned g_ctr = 0;    // last-CTA election; self-resets each run

// ---------------------------------------------------------------------------
__device__ __forceinline__ float warpSum(float x) {
#pragma unroll
    for (int o = 16; o; o >>= 1) x += __shfl_xor_sync(0xffffffffu, x, o);
    return x;
}
__device__ __forceinline__ float warpMax(float x) {
#pragma unroll
    for (int o = 16; o; o >>= 1) x = fmaxf(x, __shfl_xor_sync(0xffffffffu, x, o));
    return x;
}

__device__ __forceinline__ void imma(int& d0, int& d1, int& d2, int& d3,
                                     unsigned a0, unsigned a1, unsigned a2, unsigned a3,
                                     unsigned b0, unsigned b1) {
    asm volatile(
        "mma.sync.aligned.m16n8k32.row.col.s32.s8.s8.s32 "
        "{%0,%1,%2,%3},{%4,%5,%6,%7},{%8,%9},{%0,%1,%2,%3};"
        : "+r"(d0), "+r"(d1), "+r"(d2), "+r"(d3)
        : "r"(a0), "r"(a1), "r"(a2), "r"(a3), "r"(b0), "r"(b1));
}

// ---------------------------------------------------------------------------
// Prep (merged with gold): block = row j, 128 threads.
//  (a) row max of T -> rs_j; quantize row into the mma.m16n8k32 A-fragment
//      layout (verified R6-R15); thread k4 emits one u32.
//  (b) gold-path partial for timesteps [64j, 64j+64): threads 0..63 each
//      handle one t; block-reduce -> g_gold_part[j]. Deterministic.
// ---------------------------------------------------------------------------
__global__ void prep_kernel(const float* __restrict__ T,
                            const float* __restrict__ logit,
                            const int*   __restrict__ labels, int S) {
    __shared__ float red[4];
    __shared__ float s_mx;
    const int j   = blockIdx.x;
    const int tid = threadIdx.x;           // 0..127 == k4
    const float4 tv = reinterpret_cast<const float4*>(T + j * LNUM)[tid];

    // --- (a) row max + quantize ---
    float m = fmaxf(fmaxf(tv.x, tv.y), fmaxf(tv.z, tv.w));
    m = warpMax(m);
    if ((tid & 31) == 0) red[tid >> 5] = m;
    __syncthreads();
    if (tid == 0) {
        float mm = fmaxf(fmaxf(red[0], red[1]), fmaxf(red[2], red[3]));
        s_mx = mm;
        g_rs[j] = expf(mm) / 127.f;
    }
    __syncthreads();
    const float mx = s_mx;

    unsigned w = 0;
    w |= (unsigned)min(__float2int_rn(expf(tv.x - mx) * 127.f), 127);
    w |= (unsigned)min(__float2int_rn(expf(tv.y - mx) * 127.f), 127) << 8;
    w |= (unsigned)min(__float2int_rn(expf(tv.z - mx) * 127.f), 127) << 16;
    w |= (unsigned)min(__float2int_rn(expf(tv.w - mx) * 127.f), 127) << 24;

    int m16 = j >> 4, r = j & 15, gid = r & 7, rh = r >> 3;
    int kc  = tid >> 3;
    int tig = (tid & 7) & 3;
    int kh  = (tid & 7) >> 2;
    reinterpret_cast<unsigned*>(g_A)[((m16 * 16 + kc) * 32 + gid * 4 + tig) * 4 +
                                     (rh + 2 * kh)] = w;

    // --- (b) gold partial for timesteps [64j, 64j+64) ---
    float p = 0.f;
    if (tid < 64) {
        int t = j * 64 + tid;
        if (t < S) {
            int lt = labels[t];
            p += logit[(t << 9) + lt];
            if (t >= 1) p += T[(lt << 9) + labels[t - 1]];
        }
    }
    __syncthreads();                       // red[] reuse
    p = warpSum(p);
    if ((tid & 31) == 0) red[tid >> 5] = p;
    __syncthreads();
    if (tid == 0) g_gold_part[j] = (red[0] + red[1]) + (red[2] + red[3]);
}

// ---------------------------------------------------------------------------
// Main: one CTA = 8 chains, 256 threads = 8 warps, 2 CTAs per SM.
// GEMM: warp w owns mtiles {4w..4w+3}. Epilogue: warp w owns chain w.
// Last-arriving CTA performs the final deterministic reduction.
// ---------------------------------------------------------------------------
__global__ void __launch_bounds__(256, 2)
chunk_kernel(const float* __restrict__ logit, float* __restrict__ out,
             int S, int K) {
    __shared__ __align__(16) unsigned char vq[NCH * VPITCH];  // state, s8
    __shared__ __align__(16) float zbuf[NCH * ZP];
    __shared__ float s_rs[LNUM];
    __shared__ float s_red[8];
    __shared__ float s_m, s_s0;
    __shared__ int   s_last;
    __shared__ double sd[256];

    const int tid  = threadIdx.x;
    const int wid  = tid >> 5;          // 0..7
    const int lane = tid & 31;
    const int gid  = lane >> 2;
    const int tig  = lane & 3;

    s_rs[tid]       = g_rs[tid];
    s_rs[tid + 256] = g_rs[tid + 256];

    // --- warp-as-chain schedule (chain wid) ---
    const int cg_w   = blockIdx.x * NCH + wid;
    const int own_w  = 1 + cg_w * K;
    const int tend_w = min(own_w + K, S);
    const int t0_w   = (cg_w == 0) ? 1 : own_w - BURN;

    // --- epilogue chains for this thread: c = 2*tig + q ---
    int t0_e[2], tend_e[2];
#pragma unroll
    for (int q = 0; q < 2; ++q) {
        int cg = blockIdx.x * NCH + 2 * tig + q;
        int ow = 1 + cg * K;
        tend_e[q] = min(ow + K, S);
        t0_e[q]   = (cg == 0) ? 1 : ow - BURN;
    }

    // --- init: uniform state everywhere ---
#pragma unroll
    for (int c = 0; c < NCH; ++c) {
        vq[c * VPITCH + tid]       = 127;
        vq[c * VPITCH + tid + 256] = 127;
    }
    __syncthreads();

    float sw_reg = 127.f * (float)LNUM;   // sum of incoming state (exact int)
    float accr   = 0.f;                   // live in lane 0 of warp wid

    // --- chain 0 exact start from exp(feat_0) (block 0 only) ---
    if (blockIdx.x == 0) {
        float f0 = logit[tid], f1 = logit[tid + 256];
        float m = warpMax(fmaxf(f0, f1));
        if (lane == 0) s_red[wid] = m;
        __syncthreads();
        if (wid == 0) {
            float mm = (lane < 8) ? s_red[lane] : -1e30f;
            mm = warpMax(mm);
            if (lane == 0) s_m = mm;
        }
        __syncthreads();
        float m_all = s_m;
        int w0 = min(__float2int_rn(expf(f0 - m_all) * 127.f), 127);
        int w1 = min(__float2int_rn(expf(f1 - m_all) * 127.f), 127);
        vq[tid]       = (unsigned char)w0;
        vq[tid + 256] = (unsigned char)w1;
        float sw = warpSum((float)(w0 + w1));
        if (lane == 0) s_red[wid] = sw;
        __syncthreads();
        if (wid == 0) {
            float s = (lane < 8) ? s_red[lane] : 0.f;
            s = warpSum(s);
            if (lane == 0) s_s0 = s;
        }
        __syncthreads();
        if (wid == 0) {
            sw_reg = s_s0;
            if (lane == 0) accr = m_all - logf(127.f) + logf(s_s0);
        }
        __syncthreads();
    }

    const uint4* __restrict__ A4 = reinterpret_cast<const uint4*>(g_A);
    int jl[4];
    float rl[4], rh[4];
#pragma unroll
    for (int mi = 0; mi < 4; ++mi) {
        jl[mi] = (wid * 4 + mi) * 16 + gid;
        rl[mi] = s_rs[jl[mi]];
        rh[mi] = s_rs[jl[mi] + 8];
    }
    const int steps = BURN + K;

    for (int s = 0; s < steps; ++s) {
        // ---- prefetch logit for this step ----
        float fv[2][8];
        bool  act[2];
#pragma unroll
        for (int q = 0; q < 2; ++q) {
            int t = t0_e[q] + s;
            act[q] = (t < tend_e[q]);
            if (act[q]) {
                const float* lt = logit + ((long)t << 9);
#pragma unroll
                for (int mi = 0; mi < 4; ++mi) {
                    fv[q][mi * 2]     = lt[jl[mi]];
                    fv[q][mi * 2 + 1] = lt[jl[mi] + 8];
                }
            }
        }

        // ---- GEMM: D[512, 8] = E(s8) @ state(s8); this warp: 4 mtiles ----
        int d[4][4];
#pragma unroll
        for (int mi = 0; mi < 4; ++mi)
#pragma unroll
            for (int r = 0; r < 4; ++r) d[mi][r] = 0;

#pragma unroll
        for (int kc = 0; kc < 16; ++kc) {
            const int kb = kc * 32 + tig * 4;
            unsigned b0 = *reinterpret_cast<const unsigned*>(&vq[gid * VPITCH + kb]);
            unsigned b1 = *reinterpret_cast<const unsigned*>(&vq[gid * VPITCH + kb + 16]);
            uint4 A0 = A4[((wid * 4 + 0) * 16 + kc) * 32 + lane];
            uint4 A1 = A4[((wid * 4 + 1) * 16 + kc) * 32 + lane];
            uint4 A2 = A4[((wid * 4 + 2) * 16 + kc) * 32 + lane];
            uint4 A3 = A4[((wid * 4 + 3) * 16 + kc) * 32 + lane];
            imma(d[0][0], d[0][1], d[0][2], d[0][3], A0.x, A0.y, A0.z, A0.w, b0, b1);
            imma(d[1][0], d[1][1], d[1][2], d[1][3], A1.x, A1.y, A1.z, A1.w, b0, b1);
            imma(d[2][0], d[2][1], d[2][2], d[2][3], A2.x, A2.y, A2.z, A2.w, b0, b1);
            imma(d[3][0], d[3][1], d[3][2], d[3][3], A3.x, A3.y, A3.z, A3.w, b0, b1);
        }

        // ---- epilogue: z = exp(f) * rs_j * y  (cols: 2tig+q) ----
#pragma unroll
        for (int q = 0; q < 2; ++q) {
            if (act[q]) {
                float* zr = zbuf + (2 * tig + q) * ZP;
#pragma unroll
                for (int mi = 0; mi < 4; ++mi) {
                    zr[jl[mi]]     = __expf(fv[q][mi * 2])     * rl[mi] * (float)d[mi][q];
                    zr[jl[mi] + 8] = __expf(fv[q][mi * 2 + 1]) * rh[mi] * (float)d[mi][q + 2];
                }
            }
        }
        __syncthreads();

        // ---- warp wid: fused reduce + requant of chain wid (one reg set) ----
        {
            int t = t0_w + s;
            if (t < tend_w) {
                const float* zr = zbuf + wid * ZP;
                const float4* zb = reinterpret_cast<const float4*>(zr + lane * 16);
                float4 z0 = zb[0], z1 = zb[1], z2 = zb[2], z3 = zb[3];

                float mx = fmaxf(fmaxf(fmaxf(z0.x, z0.y), fmaxf(z0.z, z0.w)),
                                 fmaxf(fmaxf(z1.x, z1.y), fmaxf(z1.z, z1.w)));
                mx = fmaxf(mx, fmaxf(fmaxf(fmaxf(z2.x, z2.y), fmaxf(z2.z, z2.w)),
                                     fmaxf(fmaxf(z3.x, z3.y), fmaxf(z3.z, z3.w))));
                float sm = ((z0.x + z0.y) + (z0.z + z0.w)) +
                           ((z1.x + z1.y) + (z1.z + z1.w)) +
                           ((z2.x + z2.y) + (z2.z + z2.w)) +
                           ((z3.x + z3.y) + (z3.z + z3.w));
                mx = warpMax(mx);
                sm = warpSum(sm);
                float bcv = 127.f / mx;

                unsigned pk[4];
                int lsum = 0;
#pragma unroll
                for (int p = 0; p < 4; ++p) {
                    float4 z = (p == 0) ? z0 : (p == 1) ? z1 : (p == 2) ? z2 : z3;
                    int w0 = min(__float2int_rn(z.x * bcv), 127);
                    int w1 = min(__float2int_rn(z.y * bcv), 127);
                    int w2 = min(__float2int_rn(z.z * bcv), 127);
                    int w3 = min(__float2int_rn(z.w * bcv), 127);
                    lsum += w0 + w1 + w2 + w3;
                    pk[p] = (unsigned)w0 | ((unsigned)w1 << 8) |
                            ((unsigned)w2 << 16) | ((unsigned)w3 << 24);
                }
                *reinterpret_cast<uint4*>(&vq[wid * VPITCH + lane * 16]) =
                    make_uint4(pk[0], pk[1], pk[2], pk[3]);
                unsigned tot = __reduce_add_sync(0xffffffffu, (unsigned)lsum);
                if (lane == 0 && t >= own_w) accr += logf(sm) - logf(sw_reg);
                sw_reg = (float)tot;
            }
        }
        __syncthreads();
    }

    if (lane == 0) g_acc[cg_w] = accr;

    // ---- last-arriving CTA: deterministic final reduction ----
    __syncthreads();
    if (tid == 0) {
        __threadfence();                       // publish g_acc writes
        unsigned old = atomicAdd(&g_ctr, 1u);
        s_last = (old == NCTA - 1) ? 1 : 0;
    }
    __syncthreads();
    if (s_last) {
        double v = 0.0;
        for (int c = tid; c < NCHUNK; c += 256) v += (double)g_acc[c];
        for (int b = tid; b < GOLD_PARTS; b += 256) v -= (double)g_gold_part[b];
        sd[tid] = v;
        __syncthreads();
        for (int o = 128; o; o >>= 1) {
            if (tid < o) sd[tid] += sd[tid + o];
            __syncthreads();
        }
        if (tid == 0) {
            out[0] = (float)sd[0];
            g_ctr = 0;                         // reset for next graph replay
        }
    }
}

// ---------------------------------------------------------------------------
extern "C" void kernel_launch(void* const* d_in, const int* in_sizes, int n_in,
                              void* d_out, int out_size) {
    const float* logit  = (const float*)d_in[0];
    const int*   labels = (const int*)d_in[1];
    const float* T      = (const float*)d_in[2];
    const int S = in_sizes[1];                        // 32768
    const int K = (S - 1 + NCHUNK - 1) / NCHUNK;      // 14

    prep_kernel<<<LNUM, 128>>>(T, logit, labels, S);
    chunk_kernel<<<NCTA, 256>>>(logit, (float*)d_out, S, K);
}